// round 2
// baseline (speedup 1.0000x reference)
#include <cuda_runtime.h>
#include <cuda_bf16.h>
#include <math.h>
#include <float.h>

#define NN 50000
#define NE 800000
#define NG 64
#define NSLOT (NE + NN)

// ---------------- scratch (static device memory; no allocs) ----------------
__device__ float g_h1[(size_t)NN * 256];
__device__ float g_out1[(size_t)NN * 256];
__device__ float g_h2[(size_t)NN * 64];
__device__ float g_out2[(size_t)NN * 64];
__device__ float g_as1[NN * 4], g_ad1[NN * 4];
__device__ float g_as2[NN], g_ad2[NN];
__device__ int   g_deg[NN + 1];
__device__ int   g_off[NN + 1];
__device__ int   g_cursor[NN];
__device__ int   g_csr_src[NSLOT];
__device__ float g_e1[(size_t)NSLOT * 4];
__device__ float g_e2[NSLOT];
__device__ float g_sums[NG * 64];
__device__ float g_cnts[NG];
__device__ float g_vis[NG * 64];
__device__ int   g_src[NE];
__device__ int   g_dst[NE];
__device__ int   g_batch[NN];
__device__ unsigned g_flag64;   // OR of sampled odd words; 0 => int64 layout

// ---------------- init ----------------
__global__ void zero_kernel() {
    int i = blockIdx.x * blockDim.x + threadIdx.x;
    if (i == 0) g_flag64 = 0u;
    if (i < NN) g_deg[i] = 1;                 // self-loop pre-counted
    if (i < NG * 64) g_sums[i] = 0.f;
    if (i < NG) g_cnts[i] = 0.f;
}

// ---------------- dtype detect + decode ----------------
// If edge_index is int64 (little-endian, values < 2^31), odd 32-bit words are 0.
// If int32, odd words are random node ids -> OR over 4096 samples is nonzero.
__global__ void detect_kernel(const unsigned* __restrict__ e) {
    int i = blockIdx.x * blockDim.x + threadIdx.x;
    if (i < 4096) {
        unsigned w = e[2 * i + 1];
        if (w) atomicOr(&g_flag64, w);
    }
}

__global__ void decode_edges_kernel(const int* __restrict__ e) {
    int i = blockIdx.x * blockDim.x + threadIdx.x;
    if (i >= NE) return;
    if (g_flag64 == 0u) {   // int64 layout
        g_src[i] = e[2 * i];
        g_dst[i] = e[2 * NE + 2 * i];
    } else {                 // int32 layout
        g_src[i] = e[i];
        g_dst[i] = e[NE + i];
    }
}

__global__ void decode_batch_kernel(const int* __restrict__ b) {
    int i = blockIdx.x * blockDim.x + threadIdx.x;
    if (i >= NN) return;
    g_batch[i] = (g_flag64 == 0u) ? b[2 * i] : b[i];
}

// ---------------- SGEMM: C[M,N] = A[M,K] * B[K,N], row-major ----------------
// BM=64 BN=64 BK=16, 256 threads, each computes 4x4
__global__ void sgemm_kernel(const float* __restrict__ A, const float* __restrict__ B,
                             float* __restrict__ C, int M, int N, int K) {
    __shared__ float As[16][64];
    __shared__ float Bs[16][64];
    int tid = threadIdx.x;
    int tr = tid / 16, tc = tid % 16;
    int row0 = blockIdx.y * 64;
    int col0 = blockIdx.x * 64;
    float acc[4][4];
#pragma unroll
    for (int i = 0; i < 4; i++)
#pragma unroll
        for (int j = 0; j < 4; j++) acc[i][j] = 0.f;

    for (int k0 = 0; k0 < K; k0 += 16) {
#pragma unroll
        for (int i = tid; i < 64 * 16; i += 256) {
            int r = i / 16, c = i % 16;
            As[c][r] = (row0 + r < M) ? A[(size_t)(row0 + r) * K + k0 + c] : 0.f;
        }
#pragma unroll
        for (int i = tid; i < 16 * 64; i += 256) {
            int r = i / 64, c = i % 64;
            Bs[r][c] = B[(size_t)(k0 + r) * N + col0 + c];
        }
        __syncthreads();
#pragma unroll
        for (int kk = 0; kk < 16; kk++) {
            float a[4], b[4];
#pragma unroll
            for (int m = 0; m < 4; m++) a[m] = As[kk][tr * 4 + m];
#pragma unroll
            for (int n = 0; n < 4; n++) b[n] = Bs[kk][tc * 4 + n];
#pragma unroll
            for (int m = 0; m < 4; m++)
#pragma unroll
                for (int n = 0; n < 4; n++) acc[m][n] += a[m] * b[n];
        }
        __syncthreads();
    }
#pragma unroll
    for (int m = 0; m < 4; m++) {
        int r = row0 + tr * 4 + m;
        if (r < M)
#pragma unroll
            for (int n = 0; n < 4; n++) C[(size_t)r * N + col0 + tc * 4 + n] = acc[m][n];
    }
}

// ---------------- per-node attention logits: warp per (node, head) ----------------
__global__ void alphas_kernel(const float* __restrict__ h, const float* __restrict__ a_s,
                              const float* __restrict__ a_d, float* __restrict__ out_s,
                              float* __restrict__ out_d, int Nn, int H, int C) {
    int warp = (blockIdx.x * blockDim.x + threadIdx.x) >> 5;
    int lane = threadIdx.x & 31;
    if (warp >= Nn * H) return;
    int n = warp / H, hh = warp - n * H;
    const float* row = h + (size_t)n * H * C + hh * C;
    float s = 0.f, d = 0.f;
    for (int c = lane; c < C; c += 32) {
        float v = row[c];
        s += v * a_s[hh * C + c];
        d += v * a_d[hh * C + c];
    }
#pragma unroll
    for (int o = 16; o; o >>= 1) {
        s += __shfl_xor_sync(0xffffffffu, s, o);
        d += __shfl_xor_sync(0xffffffffu, d, o);
    }
    if (lane == 0) { out_s[warp] = s; out_d[warp] = d; }
}

// ---------------- CSR build ----------------
__global__ void count_kernel() {
    int i = blockIdx.x * blockDim.x + threadIdx.x;
    if (i < NE) atomicAdd(&g_deg[g_dst[i]], 1);
}

__global__ void scan_kernel() {
    __shared__ int sm[1024];
    __shared__ int carry_s;
    int tid = threadIdx.x;
    if (tid == 0) carry_s = 0;
    __syncthreads();
    for (int base = 0; base < NN; base += 1024) {
        int i = base + tid;
        int v = (i < NN) ? g_deg[i] : 0;
        sm[tid] = v;
        __syncthreads();
        for (int o = 1; o < 1024; o <<= 1) {
            int t = (tid >= o) ? sm[tid - o] : 0;
            __syncthreads();
            sm[tid] += t;
            __syncthreads();
        }
        int excl = sm[tid] - v;
        if (i < NN) { g_off[i] = carry_s + excl; g_cursor[i] = carry_s + excl; }
        __syncthreads();
        if (tid == 1023) carry_s += sm[1023];
        __syncthreads();
    }
    if (tid == 0) g_off[NN] = carry_s;
}

__global__ void fill_kernel() {
    int i = blockIdx.x * blockDim.x + threadIdx.x;
    if (i >= NE + NN) return;
    int s, d;
    if (i < NE) { s = g_src[i]; d = g_dst[i]; }
    else        { s = d = i - NE; }
    int slot = atomicAdd(&g_cursor[d], 1);
    g_csr_src[slot] = s;
#pragma unroll
    for (int hh = 0; hh < 4; hh++) {
        float e = g_as1[s * 4 + hh] + g_ad1[d * 4 + hh];
        g_e1[(size_t)slot * 4 + hh] = e > 0.f ? e : 0.2f * e;
    }
}

// ---------------- layer-1 aggregation: warp per dst node ----------------
__global__ void agg1_kernel(const float* __restrict__ b1) {
    int warp = (blockIdx.x * blockDim.x + threadIdx.x) >> 5;
    int lane = threadIdx.x & 31;
    if (warp >= NN) return;
    int beg = g_off[warp], end = g_off[warp + 1];

    float m0 = -FLT_MAX, m1 = -FLT_MAX, m2 = -FLT_MAX, m3 = -FLT_MAX;
    for (int s = beg + lane; s < end; s += 32) {
        float4 e = reinterpret_cast<const float4*>(g_e1)[s];
        m0 = fmaxf(m0, e.x); m1 = fmaxf(m1, e.y); m2 = fmaxf(m2, e.z); m3 = fmaxf(m3, e.w);
    }
#pragma unroll
    for (int o = 16; o; o >>= 1) {
        m0 = fmaxf(m0, __shfl_xor_sync(0xffffffffu, m0, o));
        m1 = fmaxf(m1, __shfl_xor_sync(0xffffffffu, m1, o));
        m2 = fmaxf(m2, __shfl_xor_sync(0xffffffffu, m2, o));
        m3 = fmaxf(m3, __shfl_xor_sync(0xffffffffu, m3, o));
    }
    float s0 = 0.f, s1 = 0.f, s2 = 0.f, s3 = 0.f;
    for (int s = beg + lane; s < end; s += 32) {
        float4 e = reinterpret_cast<const float4*>(g_e1)[s];
        s0 += __expf(e.x - m0); s1 += __expf(e.y - m1);
        s2 += __expf(e.z - m2); s3 += __expf(e.w - m3);
    }
#pragma unroll
    for (int o = 16; o; o >>= 1) {
        s0 += __shfl_xor_sync(0xffffffffu, s0, o);
        s1 += __shfl_xor_sync(0xffffffffu, s1, o);
        s2 += __shfl_xor_sync(0xffffffffu, s2, o);
        s3 += __shfl_xor_sync(0xffffffffu, s3, o);
    }
    float i0 = 1.f / (s0 + 1e-16f), i1 = 1.f / (s1 + 1e-16f);
    float i2 = 1.f / (s2 + 1e-16f), i3 = 1.f / (s3 + 1e-16f);

    float acc[8];
#pragma unroll
    for (int k = 0; k < 8; k++) acc[k] = 0.f;
    for (int s = beg; s < end; s++) {
        int srcn = g_csr_src[s];
        float4 e = reinterpret_cast<const float4*>(g_e1)[s];
        float w[4];
        w[0] = __expf(e.x - m0) * i0;
        w[1] = __expf(e.y - m1) * i1;
        w[2] = __expf(e.z - m2) * i2;
        w[3] = __expf(e.w - m3) * i3;
        const float* hr = g_h1 + (size_t)srcn * 256;
#pragma unroll
        for (int k = 0; k < 8; k++) acc[k] += w[k >> 1] * hr[lane + 32 * k];
    }
#pragma unroll
    for (int k = 0; k < 8; k++) {
        int c = lane + 32 * k;
        float v = acc[k] + b1[c];
        g_out1[(size_t)warp * 256 + c] = v > 0.f ? v : 0.f;
    }
}

// ---------------- layer-2 aggregation: warp per dst node ----------------
__global__ void agg2_kernel(const float* __restrict__ b2) {
    int warp = (blockIdx.x * blockDim.x + threadIdx.x) >> 5;
    int lane = threadIdx.x & 31;
    if (warp >= NN) return;
    int beg = g_off[warp], end = g_off[warp + 1];
    float adn = g_ad2[warp];

    float m = -FLT_MAX;
    for (int s = beg + lane; s < end; s += 32) {
        int sn = g_csr_src[s];
        float e = g_as2[sn] + adn;
        e = e > 0.f ? e : 0.2f * e;
        g_e2[s] = e;
        m = fmaxf(m, e);
    }
    __syncwarp();
#pragma unroll
    for (int o = 16; o; o >>= 1) m = fmaxf(m, __shfl_xor_sync(0xffffffffu, m, o));
    float sum = 0.f;
    for (int s = beg + lane; s < end; s += 32) sum += __expf(g_e2[s] - m);
#pragma unroll
    for (int o = 16; o; o >>= 1) sum += __shfl_xor_sync(0xffffffffu, sum, o);
    float inv = 1.f / (sum + 1e-16f);

    float a0 = 0.f, a1 = 0.f;
    for (int s = beg; s < end; s++) {
        int sn = g_csr_src[s];
        float w = __expf(g_e2[s] - m) * inv;
        a0 += w * g_h2[(size_t)sn * 64 + lane];
        a1 += w * g_h2[(size_t)sn * 64 + lane + 32];
    }
    float v0 = a0 + b2[lane], v1 = a1 + b2[lane + 32];
    g_out2[(size_t)warp * 64 + lane]      = v0 > 0.f ? v0 : 0.f;
    g_out2[(size_t)warp * 64 + lane + 32] = v1 > 0.f ? v1 : 0.f;
}

// ---------------- mean pool ----------------
__global__ void pool_kernel() {
    int idx = blockIdx.x * blockDim.x + threadIdx.x;
    if (idx >= NN * 64) return;
    int n = idx >> 6, c = idx & 63;
    int g = g_batch[n];
    atomicAdd(&g_sums[g * 64 + c], g_out2[idx]);
    if (c == 0) atomicAdd(&g_cnts[g], 1.f);
}

// ---------------- visual projection: warp per (g, o) ----------------
__global__ void vis_kernel(const float* __restrict__ visual, const float* __restrict__ wvp,
                           const float* __restrict__ bvp) {
    int warp = (blockIdx.x * blockDim.x + threadIdx.x) >> 5;
    int lane = threadIdx.x & 31;
    if (warp >= NG * 64) return;
    int g = warp >> 6, o = warp & 63;
    const float* vr = visual + (size_t)g * 2048;
    const float* wr = wvp + (size_t)o * 2048;
    float acc = 0.f;
    for (int k = lane; k < 2048; k += 32) acc += vr[k] * wr[k];
#pragma unroll
    for (int oo = 16; oo; oo >>= 1) acc += __shfl_xor_sync(0xffffffffu, acc, oo);
    if (lane == 0) {
        float v = acc + bvp[o];
        g_vis[g * 64 + o] = v > 0.f ? v : 0.f;
    }
}

// ---------------- tail: pool-normalize, v/o projections, fusion ----------------
__global__ void tail_kernel(const float* __restrict__ wv, const float* __restrict__ bv,
                            const float* __restrict__ wo, const float* __restrict__ bo,
                            const float* __restrict__ wf, const float* __restrict__ bf,
                            float* __restrict__ out) {
    __shared__ float gf[64], vis_s[64], v_s[64], ao_s[64];
    int g = blockIdx.x, o = threadIdx.x;
    float cnt = g_cnts[g];
    gf[o] = g_sums[g * 64 + o] / fmaxf(cnt, 1.f);
    vis_s[o] = g_vis[g * 64 + o];
    __syncthreads();
    float v = bv[o];
    for (int k = 0; k < 64; k++) v += gf[k] * wv[o * 64 + k];
    v_s[o] = v;
    __syncthreads();
    float ao = bo[o];
    for (int k = 0; k < 64; k++) ao += v_s[k] * wo[o * 64 + k];
    ao_s[o] = ao;
    __syncthreads();
    float r = bf[o];
    for (int k = 0; k < 64; k++) r += vis_s[k] * wf[o * 128 + k];
    for (int k = 0; k < 64; k++) r += ao_s[k] * wf[o * 128 + 64 + k];
    out[g * 64 + o] = r > 0.f ? r : 0.f;
}

// ---------------- launcher ----------------
extern "C" void kernel_launch(void* const* d_in, const int* in_sizes, int n_in,
                              void* d_out, int out_size) {
    const float* visual = (const float*)d_in[0];
    const float* x      = (const float*)d_in[1];
    const int*   eidx   = (const int*)d_in[2];      // int32 or int64 (auto-detected)
    const int*   batch  = (const int*)d_in[3];
    const float* w1  = (const float*)d_in[4];
    const float* as1 = (const float*)d_in[5];
    const float* ad1 = (const float*)d_in[6];
    const float* b1  = (const float*)d_in[7];
    const float* w2  = (const float*)d_in[8];
    const float* as2 = (const float*)d_in[9];
    const float* ad2 = (const float*)d_in[10];
    const float* b2  = (const float*)d_in[11];
    const float* wvp = (const float*)d_in[12];
    const float* bvp = (const float*)d_in[13];
    // d_in[14..17] = wq,bq,wk,bk -- mathematically dead (softmax over S=1)
    const float* wv  = (const float*)d_in[18];
    const float* bv  = (const float*)d_in[19];
    const float* wo  = (const float*)d_in[20];
    const float* bo  = (const float*)d_in[21];
    const float* wf  = (const float*)d_in[22];
    const float* bf  = (const float*)d_in[23];
    float* out = (float*)d_out;

    float* h1p;   cudaGetSymbolAddress((void**)&h1p, g_h1);
    float* out1p; cudaGetSymbolAddress((void**)&out1p, g_out1);
    float* h2p;   cudaGetSymbolAddress((void**)&h2p, g_h2);
    float* as1p;  cudaGetSymbolAddress((void**)&as1p, g_as1);
    float* ad1p;  cudaGetSymbolAddress((void**)&ad1p, g_ad1);
    float* as2p;  cudaGetSymbolAddress((void**)&as2p, g_as2);
    float* ad2p;  cudaGetSymbolAddress((void**)&ad2p, g_ad2);

    zero_kernel<<<(NN + 255) / 256, 256>>>();
    detect_kernel<<<(4096 + 255) / 256, 256>>>((const unsigned*)eidx);
    decode_edges_kernel<<<(NE + 255) / 256, 256>>>(eidx);
    decode_batch_kernel<<<(NN + 255) / 256, 256>>>(batch);
    // h1 = x @ w1  [50000,256]x[256,256]
    sgemm_kernel<<<dim3(256 / 64, (NN + 63) / 64), 256>>>(x, w1, h1p, NN, 256, 256);
    // per-node logits layer 1
    alphas_kernel<<<(NN * 4 * 32 + 255) / 256, 256>>>(h1p, as1, ad1, as1p, ad1p, NN, 4, 64);
    // CSR build
    count_kernel<<<(NE + 255) / 256, 256>>>();
    scan_kernel<<<1, 1024>>>();
    fill_kernel<<<(NE + NN + 255) / 256, 256>>>();
    // layer-1 softmax-aggregate
    agg1_kernel<<<(NN * 32 + 255) / 256, 256>>>(b1);
    // h2 = out1 @ w2  [50000,256]x[256,64]
    sgemm_kernel<<<dim3(1, (NN + 63) / 64), 256>>>(out1p, w2, h2p, NN, 64, 256);
    // per-node logits layer 2
    alphas_kernel<<<(NN * 32 + 255) / 256, 256>>>(h2p, as2, ad2, as2p, ad2p, NN, 1, 64);
    // layer-2 softmax-aggregate
    agg2_kernel<<<(NN * 32 + 255) / 256, 256>>>(b2);
    // mean pool
    pool_kernel<<<(NN * 64 + 255) / 256, 256>>>();
    // visual projection
    vis_kernel<<<(NG * 64 * 32 + 255) / 256, 256>>>(visual, wvp, bvp);
    // fused tail (MHA with S=1 degenerates: attn_out = (gf@wv.T+bv)@wo.T+bo)
    tail_kernel<<<NG, 64>>>(wv, bv, wo, bo, wf, bf, out);
}

// round 3
// speedup vs baseline: 1.7313x; 1.7313x over previous
#include <cuda_runtime.h>
#include <cuda_bf16.h>
#include <math.h>
#include <float.h>

#define NN 50000
#define NE 800000
#define NG 64
#define NSLOT (NE + NN)
#define NB_SCAN ((NN + 255) / 256)   // 196

// ---------------- scratch (static device memory; no allocs) ----------------
__device__ float g_h1[(size_t)NN * 256];
__device__ float g_out1[(size_t)NN * 256];
__device__ float g_h2[(size_t)NN * 64];
__device__ float g_as1[NN * 4], g_ad1[NN * 4];
__device__ float g_as2[NN], g_ad2[NN];
__device__ int   g_deg[NN];
__device__ int   g_part[NN];
__device__ int   g_bsum[256];
__device__ int   g_boff[256];
__device__ int   g_off[NN + 1];
__device__ int   g_cursor[NN];
__device__ int   g_csr_src[NSLOT];
__device__ float g_e1[(size_t)NSLOT * 4];
__device__ float g_sums[NG * 64];
__device__ float g_cnts[NG];
__device__ float g_vis[NG * 64];
__device__ int   g_src[NE];
__device__ int   g_dst[NE];
__device__ int   g_batch[NN];
__device__ unsigned g_flag64;   // OR of sampled odd words; 0 => int64 layout

// ---------------- init ----------------
__global__ void zero_kernel() {
    int i = blockIdx.x * blockDim.x + threadIdx.x;
    if (i == 0) { g_flag64 = 0u; g_off[NN] = NSLOT; }
    if (i < NN) g_deg[i] = 1;                 // self-loop pre-counted
    if (i < NG * 64) g_sums[i] = 0.f;
    if (i < NG) g_cnts[i] = 0.f;
}

// ---------------- dtype detect + decode ----------------
__global__ void detect_kernel(const unsigned* __restrict__ e) {
    int i = blockIdx.x * blockDim.x + threadIdx.x;
    if (i < 4096) {
        unsigned w = e[2 * i + 1];
        if (w) atomicOr(&g_flag64, w);
    }
}

// decode edges AND count in-degree in one pass
__global__ void decode_edges_kernel(const int* __restrict__ e) {
    int i = blockIdx.x * blockDim.x + threadIdx.x;
    if (i >= NE) return;
    int s, d;
    if (g_flag64 == 0u) { s = e[2 * i]; d = e[2 * NE + 2 * i]; }
    else                { s = e[i];     d = e[NE + i]; }
    g_src[i] = s;
    g_dst[i] = d;
    atomicAdd(&g_deg[d], 1);
}

__global__ void decode_batch_kernel(const int* __restrict__ b) {
    int i = blockIdx.x * blockDim.x + threadIdx.x;
    if (i >= NN) return;
    g_batch[i] = (g_flag64 == 0u) ? b[2 * i] : b[i];
}

// ---------------- SGEMM: C[M,N] = A[M,K] * B[K,N], row-major ----------------
// BK=16, 256 threads, TMxTN per thread, float4 global loads, transposed As.
template<int BM, int BN, int TM, int TN>
__global__ __launch_bounds__(256, 2)
void gemm_kernel(const float* __restrict__ A, const float* __restrict__ B,
                 float* __restrict__ C, int M, int N, int K) {
    constexpr int BK = 16;
    __shared__ float As[BK][BM];
    __shared__ float Bs[BK][BN];
    const int tid = threadIdx.x;
    const int tx = tid % (BN / TN);
    const int ty = tid / (BN / TN);
    const int row0 = blockIdx.y * BM;
    const int col0 = blockIdx.x * BN;
    float acc[TM][TN];
#pragma unroll
    for (int m = 0; m < TM; m++)
#pragma unroll
        for (int n = 0; n < TN; n++) acc[m][n] = 0.f;

    constexpr int A_VECS = BM * BK / 4;
    constexpr int B_VECS = BK * BN / 4;

    for (int k0 = 0; k0 < K; k0 += BK) {
#pragma unroll
        for (int v = tid; v < A_VECS; v += 256) {
            int r = v / (BK / 4);
            int c = (v % (BK / 4)) * 4;
            int gr = row0 + r;
            float4 t = make_float4(0.f, 0.f, 0.f, 0.f);
            if (gr < M) t = *(const float4*)&A[(size_t)gr * K + k0 + c];
            As[c + 0][r] = t.x; As[c + 1][r] = t.y;
            As[c + 2][r] = t.z; As[c + 3][r] = t.w;
        }
#pragma unroll
        for (int v = tid; v < B_VECS; v += 256) {
            int r = v / (BN / 4);
            int c = (v % (BN / 4)) * 4;
            *(float4*)&Bs[r][c] = *(const float4*)&B[(size_t)(k0 + r) * N + col0 + c];
        }
        __syncthreads();
#pragma unroll
        for (int kk = 0; kk < BK; kk++) {
            float a[TM], b[TN];
#pragma unroll
            for (int m = 0; m < TM; m++) a[m] = As[kk][ty * TM + m];
#pragma unroll
            for (int n = 0; n < TN; n++) b[n] = Bs[kk][tx * TN + n];
#pragma unroll
            for (int m = 0; m < TM; m++)
#pragma unroll
                for (int n = 0; n < TN; n++) acc[m][n] += a[m] * b[n];
        }
        __syncthreads();
    }
#pragma unroll
    for (int m = 0; m < TM; m++) {
        int r = row0 + ty * TM + m;
        if (r < M) {
#pragma unroll
            for (int n = 0; n < TN; n += 4) {
                float4 t = make_float4(acc[m][n], acc[m][n + 1], acc[m][n + 2], acc[m][n + 3]);
                *(float4*)&C[(size_t)r * N + col0 + tx * TN + n] = t;
            }
        }
    }
}

// ---------------- per-node attention logits: warp per (node, head) ----------------
__global__ void alphas_kernel(const float* __restrict__ h, const float* __restrict__ a_s,
                              const float* __restrict__ a_d, float* __restrict__ out_s,
                              float* __restrict__ out_d, int Nn, int H, int C) {
    int warp = (blockIdx.x * blockDim.x + threadIdx.x) >> 5;
    int lane = threadIdx.x & 31;
    if (warp >= Nn * H) return;
    int n = warp / H, hh = warp - n * H;
    const float* row = h + (size_t)n * H * C + hh * C;
    float s = 0.f, d = 0.f;
    for (int c = lane; c < C; c += 32) {
        float v = row[c];
        s += v * a_s[hh * C + c];
        d += v * a_d[hh * C + c];
    }
#pragma unroll
    for (int o = 16; o; o >>= 1) {
        s += __shfl_xor_sync(0xffffffffu, s, o);
        d += __shfl_xor_sync(0xffffffffu, d, o);
    }
    if (lane == 0) { out_s[warp] = s; out_d[warp] = d; }
}

// ---------------- parallel scan (3 kernels) ----------------
__global__ void scan_part_kernel() {
    __shared__ int sm[256];
    int b = blockIdx.x, t = threadIdx.x;
    int i = b * 256 + t;
    int v = (i < NN) ? g_deg[i] : 0;
    sm[t] = v;
    __syncthreads();
#pragma unroll
    for (int o = 1; o < 256; o <<= 1) {
        int u = (t >= o) ? sm[t - o] : 0;
        __syncthreads();
        sm[t] += u;
        __syncthreads();
    }
    if (i < NN) g_part[i] = sm[t];
    if (t == 255) g_bsum[b] = sm[255];
}

__global__ void scan_top_kernel() {
    __shared__ int sm[256];
    int t = threadIdx.x;
    int v = (t < NB_SCAN) ? g_bsum[t] : 0;
    sm[t] = v;
    __syncthreads();
#pragma unroll
    for (int o = 1; o < 256; o <<= 1) {
        int u = (t >= o) ? sm[t - o] : 0;
        __syncthreads();
        sm[t] += u;
        __syncthreads();
    }
    g_boff[t] = sm[t] - v;   // exclusive
}

__global__ void scan_add_kernel() {
    int i = blockIdx.x * blockDim.x + threadIdx.x;
    if (i >= NN) return;
    int off = g_boff[i >> 8] + g_part[i] - g_deg[i];
    g_off[i] = off;
    g_cursor[i] = off;
}

// ---------------- CSR fill + edge logits (leaky-relu'd), float4 store ------
__global__ void fill_kernel() {
    int i = blockIdx.x * blockDim.x + threadIdx.x;
    if (i >= NE + NN) return;
    int s, d;
    if (i < NE) { s = g_src[i]; d = g_dst[i]; }
    else        { s = d = i - NE; }
    int slot = atomicAdd(&g_cursor[d], 1);
    g_csr_src[slot] = s;
    float4 as = ((const float4*)g_as1)[s];
    float4 ad = ((const float4*)g_ad1)[d];
    float4 ev;
    ev.x = as.x + ad.x; ev.x = ev.x > 0.f ? ev.x : 0.2f * ev.x;
    ev.y = as.y + ad.y; ev.y = ev.y > 0.f ? ev.y : 0.2f * ev.y;
    ev.z = as.z + ad.z; ev.z = ev.z > 0.f ? ev.z : 0.2f * ev.z;
    ev.w = as.w + ad.w; ev.w = ev.w > 0.f ? ev.w : 0.2f * ev.w;
    ((float4*)g_e1)[slot] = ev;
}

// ---------------- layer-1 aggregation: warp per dst node, float4 lanes -----
// lane owns cols [lane*4, lane*4+4) (head lane/16) and [128+lane*4, ...) (head 2+lane/16)
__global__ void agg1_kernel(const float* __restrict__ b1) {
    int warp = (blockIdx.x * blockDim.x + threadIdx.x) >> 5;
    int lane = threadIdx.x & 31;
    if (warp >= NN) return;
    int beg = g_off[warp], end = g_off[warp + 1];

    float m0 = -FLT_MAX, m1 = -FLT_MAX, m2 = -FLT_MAX, m3 = -FLT_MAX;
    for (int s = beg + lane; s < end; s += 32) {
        float4 e = ((const float4*)g_e1)[s];
        m0 = fmaxf(m0, e.x); m1 = fmaxf(m1, e.y); m2 = fmaxf(m2, e.z); m3 = fmaxf(m3, e.w);
    }
#pragma unroll
    for (int o = 16; o; o >>= 1) {
        m0 = fmaxf(m0, __shfl_xor_sync(0xffffffffu, m0, o));
        m1 = fmaxf(m1, __shfl_xor_sync(0xffffffffu, m1, o));
        m2 = fmaxf(m2, __shfl_xor_sync(0xffffffffu, m2, o));
        m3 = fmaxf(m3, __shfl_xor_sync(0xffffffffu, m3, o));
    }
    float s0 = 0.f, s1 = 0.f, s2 = 0.f, s3 = 0.f;
    for (int s = beg + lane; s < end; s += 32) {
        float4 e = ((const float4*)g_e1)[s];
        s0 += __expf(e.x - m0); s1 += __expf(e.y - m1);
        s2 += __expf(e.z - m2); s3 += __expf(e.w - m3);
    }
#pragma unroll
    for (int o = 16; o; o >>= 1) {
        s0 += __shfl_xor_sync(0xffffffffu, s0, o);
        s1 += __shfl_xor_sync(0xffffffffu, s1, o);
        s2 += __shfl_xor_sync(0xffffffffu, s2, o);
        s3 += __shfl_xor_sync(0xffffffffu, s3, o);
    }
    // per-lane head selection
    bool hi = (lane & 16) != 0;
    float ma = hi ? m1 : m0;                    // head of cols [0,128)
    float mb = hi ? m3 : m2;                    // head of cols [128,256)
    float ia = 1.f / ((hi ? s1 : s0) + 1e-16f);
    float ib = 1.f / ((hi ? s3 : s2) + 1e-16f);

    float4 acc0 = make_float4(0.f, 0.f, 0.f, 0.f);
    float4 acc1 = make_float4(0.f, 0.f, 0.f, 0.f);
    for (int s = beg; s < end; s++) {
        int srcn = g_csr_src[s];                 // broadcast
        float4 e = ((const float4*)g_e1)[s];     // broadcast
        float ea = hi ? e.y : e.x;
        float eb = hi ? e.w : e.z;
        float wa = __expf(ea - ma) * ia;
        float wb = __expf(eb - mb) * ib;
        const float4* hr = (const float4*)(g_h1 + (size_t)srcn * 256);
        float4 ha = hr[lane];
        float4 hb = hr[lane + 32];
        acc0.x += wa * ha.x; acc0.y += wa * ha.y; acc0.z += wa * ha.z; acc0.w += wa * ha.w;
        acc1.x += wb * hb.x; acc1.y += wb * hb.y; acc1.z += wb * hb.z; acc1.w += wb * hb.w;
    }
    const float4* b1v = (const float4*)b1;
    float4 ba = b1v[lane], bb = b1v[lane + 32];
    float4 va, vb;
    va.x = fmaxf(acc0.x + ba.x, 0.f); va.y = fmaxf(acc0.y + ba.y, 0.f);
    va.z = fmaxf(acc0.z + ba.z, 0.f); va.w = fmaxf(acc0.w + ba.w, 0.f);
    vb.x = fmaxf(acc1.x + bb.x, 0.f); vb.y = fmaxf(acc1.y + bb.y, 0.f);
    vb.z = fmaxf(acc1.z + bb.z, 0.f); vb.w = fmaxf(acc1.w + bb.w, 0.f);
    float4* outr = (float4*)(g_out1 + (size_t)warp * 256);
    outr[lane] = va;
    outr[lane + 32] = vb;
}

// ---------------- layer-2 aggregation + fused mean-pool --------------------
// warp per dst node; lane owns cols [lane*2, lane*2+2)
__global__ void agg2_kernel(const float* __restrict__ b2) {
    int warp = (blockIdx.x * blockDim.x + threadIdx.x) >> 5;
    int lane = threadIdx.x & 31;
    if (warp >= NN) return;
    int beg = g_off[warp], end = g_off[warp + 1];
    float adn = g_ad2[warp];

    float m = -FLT_MAX;
    for (int s = beg + lane; s < end; s += 32) {
        float e = g_as2[g_csr_src[s]] + adn;
        e = e > 0.f ? e : 0.2f * e;
        m = fmaxf(m, e);
    }
#pragma unroll
    for (int o = 16; o; o >>= 1) m = fmaxf(m, __shfl_xor_sync(0xffffffffu, m, o));
    float sum = 0.f;
    for (int s = beg + lane; s < end; s += 32) {
        float e = g_as2[g_csr_src[s]] + adn;
        e = e > 0.f ? e : 0.2f * e;
        sum += __expf(e - m);
    }
#pragma unroll
    for (int o = 16; o; o >>= 1) sum += __shfl_xor_sync(0xffffffffu, sum, o);
    float inv = 1.f / (sum + 1e-16f);

    float a0 = 0.f, a1 = 0.f;
    for (int s = beg; s < end; s++) {
        int sn = g_csr_src[s];                   // broadcast
        float e = g_as2[sn] + adn;               // broadcast line
        e = e > 0.f ? e : 0.2f * e;
        float w = __expf(e - m) * inv;
        float2 hv = ((const float2*)(g_h2 + (size_t)sn * 64))[lane];
        a0 += w * hv.x;
        a1 += w * hv.y;
    }
    float2 bb = ((const float2*)b2)[lane];
    float v0 = fmaxf(a0 + bb.x, 0.f);
    float v1 = fmaxf(a1 + bb.y, 0.f);
    // fused mean pool (g_out2 eliminated)
    int g = g_batch[warp];
    atomicAdd(&g_sums[g * 64 + lane * 2], v0);
    atomicAdd(&g_sums[g * 64 + lane * 2 + 1], v1);
    if (lane == 0) atomicAdd(&g_cnts[g], 1.f);
}

// ---------------- visual projection: warp per (g, o), float4 ----------------
__global__ void vis_kernel(const float* __restrict__ visual, const float* __restrict__ wvp,
                           const float* __restrict__ bvp) {
    int warp = (blockIdx.x * blockDim.x + threadIdx.x) >> 5;
    int lane = threadIdx.x & 31;
    if (warp >= NG * 64) return;
    int g = warp >> 6, o = warp & 63;
    const float4* vr = (const float4*)(visual + (size_t)g * 2048);
    const float4* wr = (const float4*)(wvp + (size_t)o * 2048);
    float acc = 0.f;
    for (int k = lane; k < 512; k += 32) {
        float4 a = vr[k], w = wr[k];
        acc += a.x * w.x + a.y * w.y + a.z * w.z + a.w * w.w;
    }
#pragma unroll
    for (int oo = 16; oo; oo >>= 1) acc += __shfl_xor_sync(0xffffffffu, acc, oo);
    if (lane == 0) {
        float v = acc + bvp[o];
        g_vis[g * 64 + o] = v > 0.f ? v : 0.f;
    }
}

// ---------------- tail: pool-normalize, v/o projections, fusion ----------------
__global__ void tail_kernel(const float* __restrict__ wv, const float* __restrict__ bv,
                            const float* __restrict__ wo, const float* __restrict__ bo,
                            const float* __restrict__ wf, const float* __restrict__ bf,
                            float* __restrict__ out) {
    __shared__ float gf[64], vis_s[64], v_s[64], ao_s[64];
    int g = blockIdx.x, o = threadIdx.x;
    float cnt = g_cnts[g];
    gf[o] = g_sums[g * 64 + o] / fmaxf(cnt, 1.f);
    vis_s[o] = g_vis[g * 64 + o];
    __syncthreads();
    float v = bv[o];
    for (int k = 0; k < 64; k++) v += gf[k] * wv[o * 64 + k];
    v_s[o] = v;
    __syncthreads();
    float ao = bo[o];
    for (int k = 0; k < 64; k++) ao += v_s[k] * wo[o * 64 + k];
    ao_s[o] = ao;
    __syncthreads();
    float r = bf[o];
    for (int k = 0; k < 64; k++) r += vis_s[k] * wf[o * 128 + k];
    for (int k = 0; k < 64; k++) r += ao_s[k] * wf[o * 128 + 64 + k];
    out[g * 64 + o] = r > 0.f ? r : 0.f;
}

// ---------------- launcher ----------------
extern "C" void kernel_launch(void* const* d_in, const int* in_sizes, int n_in,
                              void* d_out, int out_size) {
    const float* visual = (const float*)d_in[0];
    const float* x      = (const float*)d_in[1];
    const int*   eidx   = (const int*)d_in[2];      // int32 or int64 (auto-detected)
    const int*   batch  = (const int*)d_in[3];
    const float* w1  = (const float*)d_in[4];
    const float* as1 = (const float*)d_in[5];
    const float* ad1 = (const float*)d_in[6];
    const float* b1  = (const float*)d_in[7];
    const float* w2  = (const float*)d_in[8];
    const float* as2 = (const float*)d_in[9];
    const float* ad2 = (const float*)d_in[10];
    const float* b2  = (const float*)d_in[11];
    const float* wvp = (const float*)d_in[12];
    const float* bvp = (const float*)d_in[13];
    // d_in[14..17] = wq,bq,wk,bk -- mathematically dead (softmax over S=1)
    const float* wv  = (const float*)d_in[18];
    const float* bv  = (const float*)d_in[19];
    const float* wo  = (const float*)d_in[20];
    const float* bo  = (const float*)d_in[21];
    const float* wf  = (const float*)d_in[22];
    const float* bf  = (const float*)d_in[23];
    float* out = (float*)d_out;

    float* h1p;   cudaGetSymbolAddress((void**)&h1p, g_h1);
    float* out1p; cudaGetSymbolAddress((void**)&out1p, g_out1);
    float* h2p;   cudaGetSymbolAddress((void**)&h2p, g_h2);
    float* as1p;  cudaGetSymbolAddress((void**)&as1p, g_as1);
    float* ad1p;  cudaGetSymbolAddress((void**)&ad1p, g_ad1);
    float* as2p;  cudaGetSymbolAddress((void**)&as2p, g_as2);
    float* ad2p;  cudaGetSymbolAddress((void**)&ad2p, g_ad2);

    zero_kernel<<<(NN + 255) / 256, 256>>>();
    detect_kernel<<<16, 256>>>((const unsigned*)eidx);
    decode_edges_kernel<<<(NE + 255) / 256, 256>>>(eidx);   // + degree count
    decode_batch_kernel<<<(NN + 255) / 256, 256>>>(batch);
    // h1 = x @ w1  [50000,256]x[256,256]
    gemm_kernel<128, 128, 8, 8><<<dim3(2, (NN + 127) / 128), 256>>>(x, w1, h1p, NN, 256, 256);
    // per-node logits layer 1
    alphas_kernel<<<(NN * 4 * 32 + 255) / 256, 256>>>(h1p, as1, ad1, as1p, ad1p, NN, 4, 64);
    // CSR offsets (parallel scan)
    scan_part_kernel<<<NB_SCAN, 256>>>();
    scan_top_kernel<<<1, 256>>>();
    scan_add_kernel<<<(NN + 255) / 256, 256>>>();
    fill_kernel<<<(NE + NN + 255) / 256, 256>>>();
    // layer-1 softmax-aggregate
    agg1_kernel<<<(NN * 32 + 255) / 256, 256>>>(b1);
    // h2 = out1 @ w2  [50000,256]x[256,64]
    gemm_kernel<128, 64, 8, 4><<<dim3(1, (NN + 127) / 128), 256>>>(out1p, w2, h2p, NN, 64, 256);
    // per-node logits layer 2
    alphas_kernel<<<(NN * 32 + 255) / 256, 256>>>(h2p, as2, ad2, as2p, ad2p, NN, 1, 64);
    // layer-2 softmax-aggregate + fused mean pool
    agg2_kernel<<<(NN * 32 + 255) / 256, 256>>>(b2);
    // visual projection
    vis_kernel<<<(NG * 64 * 32 + 255) / 256, 256>>>(visual, wvp, bvp);
    // fused tail (MHA with S=1 degenerates: attn_out = (gf@wv.T+bv)@wo.T+bo)
    tail_kernel<<<NG, 64>>>(wv, bv, wo, bo, wf, bf, out);
}